// round 7
// baseline (speedup 1.0000x reference)
#include <cuda_runtime.h>
#include <cstdint>

// Two-simplicial attention, B=2, S=2048, H=4, D=64, W1=W2=64 (A=C=65).
// 1 position per CTA, 256 threads, 2 CTAs/SM.
// R7 = R6 + V1/V2 via cp.async.bulk (waited after phase 3) + K2T stride 67.

constexpr int Bc = 2, Sc = 2048, Hc = 4, Dc = 64;
constexpr float SCALE_F = 0.125f;
constexpr int NT = 256;

// ---- smem layout (floats) ----
constexpr int OFF_MBAR = 0;                   // 8 B mbarrier
constexpr int OFF_K1Q  = 4;                   // [65][64] q-folded k1
constexpr int OFF_K2T  = OFF_K1Q + 65 * 64;   // [64][67] k2 transposed
constexpr int OFF_V1   = OFF_K2T + 64 * 67;   // [65][64] (16B-aligned)
constexpr int OFF_V2   = OFF_V1 + 65 * 64;    // [65][64] (16B-aligned)
constexpr int OFF_W    = OFF_V2 + 65 * 64;    // [72][68]
constexpr int OFF_NP   = OFF_W + 72 * 68;     // [8][64]
constexpr int OFF_DEN  = OFF_NP + 8 * 64;     // [8]
constexpr int SMEM_FLOATS = OFF_DEN + 8;
constexpr int SMEM_BYTES = SMEM_FLOATS * 4;   // ~86.7 KB -> 2 CTAs/SM

typedef unsigned long long ull;

__device__ __forceinline__ void ffma2(ull& acc, ull a, ull b) {
    asm("fma.rn.f32x2 %0, %1, %2, %0;" : "+l"(acc) : "l"(a), "l"(b));
}
__device__ __forceinline__ ull pack2(float lo, float hi) {
    ull r;
    asm("mov.b64 %0, {%1, %2};" : "=l"(r) : "f"(lo), "f"(hi));
    return r;
}
__device__ __forceinline__ float2 unpack2(ull v) {
    float2 f;
    asm("mov.b64 {%0, %1}, %2;" : "=f"(f.x), "=f"(f.y) : "l"(v));
    return f;
}
__device__ __forceinline__ uint32_t smem_u32(const void* p) {
    uint32_t a;
    asm("{ .reg .u64 t; cvta.to.shared.u64 t, %1; cvt.u32.u64 %0, t; }"
        : "=r"(a) : "l"(p));
    return a;
}
__device__ __forceinline__ void mbar_init(uint32_t mbar, uint32_t cnt) {
    asm volatile("mbarrier.init.shared.b64 [%0], %1;" :: "r"(mbar), "r"(cnt) : "memory");
}
__device__ __forceinline__ void mbar_expect_tx(uint32_t mbar, uint32_t bytes) {
    asm volatile("mbarrier.arrive.expect_tx.shared.b64 _, [%0], %1;"
                 :: "r"(mbar), "r"(bytes) : "memory");
}
__device__ __forceinline__ void bulk_cp(uint32_t dst, const void* src,
                                        uint32_t bytes, uint32_t mbar) {
    asm volatile(
        "cp.async.bulk.shared::cluster.global.mbarrier::complete_tx::bytes "
        "[%0], [%1], %2, [%3];"
        :: "r"(dst), "l"(src), "r"(bytes), "r"(mbar) : "memory");
}
__device__ __forceinline__ void mbar_wait(uint32_t mbar, uint32_t parity) {
    asm volatile(
        "{\n\t"
        ".reg .pred P;\n\t"
        "WAIT_%=:\n\t"
        "mbarrier.try_wait.parity.acquire.cta.shared::cta.b64 P, [%0], %1;\n\t"
        "@P bra WAIT_DONE_%=;\n\t"
        "bra.uni WAIT_%=;\n\t"
        "WAIT_DONE_%=:\n\t"
        "}"
        :: "r"(mbar), "r"(parity) : "memory");
}

__global__ void __launch_bounds__(NT, 2)
tsa_kernel(const float* __restrict__ q,
           const float* __restrict__ k1,
           const float* __restrict__ k2,
           const float* __restrict__ v1,
           const float* __restrict__ v2,
           float* __restrict__ out) {
    extern __shared__ float sm[];
    const int tid = threadIdx.x;
    const int bid = blockIdx.x;
    const int h = bid & 3;
    const int s = (bid >> 2) & 2047;
    const int b = bid >> 13;

    const uint32_t smb = smem_u32(sm);
    const uint32_t mbar = smb + OFF_MBAR * 4;

    if (tid == 0) mbar_init(mbar, 1);
    __syncthreads();   // mbarrier init visible before any complete_tx

    // ---- async V1/V2 window copies (130 rows x 256B), waited after phase 3 ----
    if (tid == 0) mbar_expect_tx(mbar, 130 * 256);
    if (tid < 130) {
        int r = (tid < 65) ? tid : tid - 65;
        int g = s - 64 + r; if (g < 0) g = 0;
        const float* src = ((tid < 65) ? v1 : v2) + ((b * Sc + g) * Hc + h) * Dc;
        uint32_t dst = smb + 4 * (((tid < 65) ? OFF_V1 : OFF_V2) + r * 64);
        bulk_cp(dst, src, 256, mbar);
    }

    // ---- zero W cols 64..67 for rows 65..71 (read in phase 4, never written) ----
    if (tid >= 192 && tid < 220) {
        int t = tid - 192;
        sm[OFF_W + (65 + (t >> 2)) * 68 + 64 + (t & 3)] = 0.0f;
    }

    // ================= stage A: K loads + transpose/fold =================
    const int qb = ((b * Sc + s) * Hc + h) * Dc;
    const int dq = tid & 15;
    const float4 qv = *(const float4*)&q[qb + dq * 4];

    for (int i = tid; i < 65 * 16; i += NT) {
        int r = i >> 4;
        int g = s - 64 + r; if (g < 0) g = 0;
        int off = ((b * Sc + g) * Hc + h) * Dc + dq * 4;
        float4 cv = *(const float4*)&k2[off];
        int d0 = dq * 4;
        sm[OFF_K2T + (d0 + 0) * 67 + r] = cv.x;
        sm[OFF_K2T + (d0 + 1) * 67 + r] = cv.y;
        sm[OFF_K2T + (d0 + 2) * 67 + r] = cv.z;
        sm[OFF_K2T + (d0 + 3) * 67 + r] = cv.w;
        float4 kv = *(const float4*)&k1[off];
        kv.x *= qv.x; kv.y *= qv.y; kv.z *= qv.z; kv.w *= qv.w;
        *(float4*)&sm[OFF_K1Q + r * 64 + d0] = kv;
    }
    __syncthreads();

    // ================= phase 3: scores + exp =================
    const int wid = tid >> 5, lane = tid & 31;
    const int a0 = wid * 9;
    const int amin = 64 - s;

    int rowi[9];
#pragma unroll
    for (int i = 0; i < 9; i++) {
        int r = a0 + i;
        rowi[i] = (r > 64) ? 64 : r;
    }

    ull acc[9][2];
#pragma unroll
    for (int i = 0; i < 9; i++) { acc[i][0] = 0ull; acc[i][1] = 0ull; }

    const float* c0 = &sm[OFF_K2T + lane];
    const float* c1 = &sm[OFF_K2T + lane + 32];

#pragma unroll 4
    for (int dqi = 0; dqi < 16; dqi++) {
        int d0 = dqi * 4;
        float c00 = c0[(d0    ) * 67], c01 = c1[(d0    ) * 67];
        float c10 = c0[(d0 + 1) * 67], c11 = c1[(d0 + 1) * 67];
        float c20 = c0[(d0 + 2) * 67], c21 = c1[(d0 + 2) * 67];
        float c30 = c0[(d0 + 3) * 67], c31 = c1[(d0 + 3) * 67];
        ull kA0 = pack2(c00, c10), kA1 = pack2(c01, c11);
        ull kB0 = pack2(c20, c30), kB1 = pack2(c21, c31);
#pragma unroll
        for (int i = 0; i < 9; i++) {
            ulonglong2 a4 = *(const ulonglong2*)&sm[OFF_K1Q + rowi[i] * 64 + d0];
            ffma2(acc[i][0], a4.x, kA0);
            ffma2(acc[i][1], a4.x, kA1);
            ffma2(acc[i][0], a4.y, kB0);
            ffma2(acc[i][1], a4.y, kB1);
        }
    }

    float dloc = 0.0f;
#pragma unroll
    for (int i = 0; i < 9; i++) {
        int a = a0 + i;
        bool av = (a < 65) && (a >= amin);
#pragma unroll
        for (int jc = 0; jc < 2; jc++) {
            int c = lane + 32 * jc;
            float2 t = unpack2(acc[i][jc]);
            float sc = (t.x + t.y) * SCALE_F;
            float wv = 0.0f;
            if (av && c >= amin) { wv = __expf(sc); dloc += wv; }
            sm[OFF_W + a * 68 + c] = wv;   // rows >= 65 get zeros
        }
    }
    // tail column c = 64 (always >= amin); zero pad cols 65..67
    {
        float k2a = sm[OFF_K2T + (2 * lane    ) * 67 + 64];
        float k2b = sm[OFF_K2T + (2 * lane + 1) * 67 + 64];
#pragma unroll
        for (int i = 0; i < 9; i++) {
            float2 kf = *(const float2*)&sm[OFF_K1Q + rowi[i] * 64 + lane * 2];
            float t = kf.x * k2a + kf.y * k2b;
#pragma unroll
            for (int o = 16; o; o >>= 1) t += __shfl_xor_sync(0xFFFFFFFFu, t, o);
            if (lane == 0) {
                int a = a0 + i;
                if (a < 65) {
                    float wv = (a >= amin) ? __expf(t * SCALE_F) : 0.0f;
                    dloc += wv;
                    sm[OFF_W + a * 68 + 64] = wv;
                    sm[OFF_W + a * 68 + 65] = 0.0f;
                    sm[OFF_W + a * 68 + 66] = 0.0f;
                    sm[OFF_W + a * 68 + 67] = 0.0f;
                }
            }
        }
    }
#pragma unroll
    for (int o = 16; o; o >>= 1) dloc += __shfl_xor_sync(0xFFFFFFFFu, dloc, o);
    if (lane == 0) sm[OFF_DEN + wid] = dloc;
    __syncwarp();                 // W rows of this warp visible within warp

    mbar_wait(mbar, 0);           // V1/V2 bulk copies complete

    // ================= phase 4: num = sum_a v1[a] * (W[a,:] @ V2) =================
    ull tmp[9][2];
#pragma unroll
    for (int i = 0; i < 9; i++) { tmp[i][0] = 0ull; tmp[i][1] = 0ull; }

#pragma unroll 4
    for (int cq = 0; cq < 16; cq++) {
        int c = cq * 4;
        float va0 = sm[OFF_V2 + (c    ) * 64 + lane];
        float va1 = sm[OFF_V2 + (c + 1) * 64 + lane];
        float va2 = sm[OFF_V2 + (c + 2) * 64 + lane];
        float va3 = sm[OFF_V2 + (c + 3) * 64 + lane];
        float vb0 = sm[OFF_V2 + (c    ) * 64 + lane + 32];
        float vb1 = sm[OFF_V2 + (c + 1) * 64 + lane + 32];
        float vb2 = sm[OFF_V2 + (c + 2) * 64 + lane + 32];
        float vb3 = sm[OFF_V2 + (c + 3) * 64 + lane + 32];
        ull vp0 = pack2(va0, va1), vp1 = pack2(va2, va3);
        ull vq0 = pack2(vb0, vb1), vq1 = pack2(vb2, vb3);
#pragma unroll
        for (int i = 0; i < 9; i++) {
            ulonglong2 wq = *(const ulonglong2*)&sm[OFF_W + (a0 + i) * 68 + c];
            ffma2(tmp[i][0], wq.x, vp0);
            ffma2(tmp[i][1], wq.x, vq0);
            ffma2(tmp[i][0], wq.y, vp1);
            ffma2(tmp[i][1], wq.y, vq1);
        }
    }
    // tail c = 64 + v1 contraction
    float v64a = sm[OFF_V2 + 64 * 64 + lane];
    float v64b = sm[OFF_V2 + 64 * 64 + lane + 32];
    float ns0 = 0.0f, ns1 = 0.0f;
#pragma unroll
    for (int i = 0; i < 9; i++) {
        float w64 = sm[OFF_W + (a0 + i) * 68 + 64];
        float2 t0 = unpack2(tmp[i][0]);
        float2 t1 = unpack2(tmp[i][1]);
        float ta = t0.x + t0.y + w64 * v64a;
        float tb = t1.x + t1.y + w64 * v64b;
        ta *= sm[OFF_V1 + rowi[i] * 64 + lane];        // invalid rows: all-zero W
        tb *= sm[OFF_V1 + rowi[i] * 64 + lane + 32];
        ns0 += ta;
        ns1 += tb;
    }
    sm[OFF_NP + wid * 64 + lane]      = ns0;
    sm[OFF_NP + wid * 64 + lane + 32] = ns1;
    __syncthreads();

    // ================= epilogue =================
    if (tid < 64) {
        float den = 1e-8f;
#pragma unroll
        for (int w = 0; w < 8; w++) den += sm[OFF_DEN + w];
        float num = 0.0f;
#pragma unroll
        for (int w = 0; w < 8; w++) num += sm[OFF_NP + w * 64 + tid];
        out[qb + tid] = num / den;
    }
}

extern "C" void kernel_launch(void* const* d_in, const int* in_sizes, int n_in,
                              void* d_out, int out_size) {
    const float* q  = (const float*)d_in[0];
    const float* k1 = (const float*)d_in[1];
    const float* k2 = (const float*)d_in[2];
    const float* v1 = (const float*)d_in[3];
    const float* v2 = (const float*)d_in[4];
    float* out = (float*)d_out;

    cudaFuncSetAttribute(tsa_kernel, cudaFuncAttributeMaxDynamicSharedMemorySize,
                         SMEM_BYTES);
    dim3 grid(Bc * Sc * Hc);
    tsa_kernel<<<grid, NT, SMEM_BYTES>>>(q, k1, k2, v1, v2, out);
}